// round 2
// baseline (speedup 1.0000x reference)
#include <cuda_runtime.h>

#define B_    64
#define S_    512
#define DIN   512
#define NCAP  32
#define DCAP  64
#define EPSQ  1e-7f

// ---------------- scratch (device globals; no allocations) ----------------
__device__ float g_t[B_ * DIN];            // column sums of U (iter-0 "v", n-independent)
__device__ float g_v[B_ * NCAP * DIN];     // v[b,n,i] = sum_s c * U
__device__ float g_w[B_ * NCAP * DIN];     // w[b,n,i] = sum_d out * W
__device__ float g_c[B_ * S_ * NCAP];      // logits -> (in-place softmax) -> c, layout (b,s,n)

// ---------------- t[b,i] = sum_s U[b,s,i] ----------------
__global__ __launch_bounds__(128) void colsum_k(const float* __restrict__ U) {
    int b = blockIdx.y;
    int i = blockIdx.x * 128 + threadIdx.x;
    const float* p = U + (size_t)b * S_ * DIN + i;
    float a0 = 0.f, a1 = 0.f, a2 = 0.f, a3 = 0.f;
    #pragma unroll 4
    for (int s = 0; s < S_; s += 4) {
        a0 += p[(size_t)(s    ) * DIN];
        a1 += p[(size_t)(s + 1) * DIN];
        a2 += p[(size_t)(s + 2) * DIN];
        a3 += p[(size_t)(s + 3) * DIN];
    }
    g_t[b * DIN + i] = a0 + a1 + a2 + a3;
}

// ---------------- outputs[b,n,:] = squash(v[b,n,:] @ W[:, n*64:+64]) ----------------
// grid (8 b-groups, 32 n), block 256. W block per n = 128KB, reused across 8 b's via L1.
__global__ __launch_bounds__(256) void out_k(const float* __restrict__ W,
                                             float* __restrict__ out, int bcast) {
    int n  = blockIdx.y;
    int b0 = blockIdx.x * 8;
    __shared__ float sv[DIN];
    __shared__ float red[256];
    __shared__ float so[DCAP];
    __shared__ float swsum[2];
    const float* Wn = W + n * DCAP;
    int tid  = threadIdx.x;
    int d    = tid & 63;
    int part = tid >> 6;   // 0..3, each covers 128 of the 512 i's
    for (int bb = 0; bb < 8; ++bb) {
        int b = b0 + bb;
        const float* v = bcast ? (g_t + (size_t)b * DIN)
                               : (g_v + ((size_t)b * NCAP + n) * DIN);
        sv[tid]       = v[tid];
        sv[256 + tid] = v[256 + tid];
        __syncthreads();
        float a0 = 0.f, a1 = 0.f, a2 = 0.f, a3 = 0.f;
        int ib = part * 128;
        #pragma unroll 8
        for (int k = 0; k < 128; k += 4) {
            a0 += sv[ib + k    ] * Wn[(size_t)(ib + k    ) * 2048 + d];
            a1 += sv[ib + k + 1] * Wn[(size_t)(ib + k + 1) * 2048 + d];
            a2 += sv[ib + k + 2] * Wn[(size_t)(ib + k + 2) * 2048 + d];
            a3 += sv[ib + k + 3] * Wn[(size_t)(ib + k + 3) * 2048 + d];
        }
        red[tid] = a0 + a1 + a2 + a3;
        __syncthreads();
        if (part == 0) {
            float o = red[d] + red[64 + d] + red[128 + d] + red[192 + d];
            if (bcast) o *= (1.0f / 32.0f);   // uniform softmax of zero logits
            so[d] = o;
            float sq = o * o;
            #pragma unroll
            for (int off = 16; off; off >>= 1)
                sq += __shfl_xor_sync(0xffffffffu, sq, off);
            if ((tid & 31) == 0) swsum[tid >> 5] = sq;
        }
        __syncthreads();
        if (part == 0) {
            float rn = rsqrtf(swsum[0] + swsum[1] + EPSQ);
            out[((size_t)b * NCAP + n) * DCAP + d] = so[d] * rn;
        }
        __syncthreads();
    }
}

// ---------------- w[b,n,i] = sum_d out[b,n,d] * W[i, n*64+d] ----------------
// grid (8 b-groups, 32 n), block 512 (thread = i). W block reused across b via L1.
__global__ __launch_bounds__(512) void w_k(const float* __restrict__ outp,
                                           const float* __restrict__ W) {
    int n  = blockIdx.y;
    int b0 = blockIdx.x * 8;
    __shared__ float so[DCAP];
    int tid = threadIdx.x;
    const float4* wr = (const float4*)(W + n * DCAP + (size_t)tid * 2048);
    for (int bb = 0; bb < 8; ++bb) {
        int b = b0 + bb;
        if (tid < DCAP) so[tid] = outp[((size_t)b * NCAP + n) * DCAP + tid];
        __syncthreads();
        float acc = 0.f;
        #pragma unroll
        for (int q = 0; q < 16; ++q) {
            float4 wv = wr[q];
            acc += so[q * 4 + 0] * wv.x + so[q * 4 + 1] * wv.y
                 + so[q * 4 + 2] * wv.z + so[q * 4 + 3] * wv.w;
        }
        g_w[((size_t)b * NCAP + n) * DIN + tid] = acc;
        __syncthreads();
    }
}

// ---------------- blog[b,s,n] = sum_i U[b,s,i] * w[b,n,i] ----------------
// per-b GEMM (512s x 512i) @ (512i x 32n), tile 128s x 32n, grid (4,64), block 256.
__global__ __launch_bounds__(256) void blog_k(const float* __restrict__ U) {
    int b  = blockIdx.y;
    int s0 = blockIdx.x * 128;
    __shared__ float su[128 * 33];   // [s][k], pad 33
    __shared__ float sw[32 * 33];    // [k][n], pad 33
    int tid = threadIdx.x;
    int tn  = (tid & 7) * 4;         // n0 (covers 0..31)
    int ts  = (tid >> 3) * 4;        // s0 local (covers 0..127)
    float acc[4][4] = {};
    const float* Ub = U   + (size_t)b * S_ * DIN;
    const float* wb = g_w + (size_t)b * NCAP * DIN;
    for (int k0 = 0; k0 < DIN; k0 += 32) {
        {   // U tile 128s x 32k
            int k  = tid & 31;
            int sb = tid >> 5;       // 0..7
            #pragma unroll
            for (int r = 0; r < 16; ++r) {
                int s = sb + r * 8;
                su[s * 33 + k] = Ub[(size_t)(s0 + s) * DIN + k0 + k];
            }
        }
        {   // w tile 32k x 32n
            int k  = tid & 31;
            int nb = tid >> 5;
            #pragma unroll
            for (int r = 0; r < 4; ++r) {
                int n = nb + r * 8;
                sw[k * 33 + n] = wb[(size_t)n * DIN + k0 + k];
            }
        }
        __syncthreads();
        #pragma unroll
        for (int kk = 0; kk < 32; ++kk) {
            float av[4], bv[4];
            #pragma unroll
            for (int j = 0; j < 4; ++j) av[j] = su[(ts + j) * 33 + kk];
            #pragma unroll
            for (int j = 0; j < 4; ++j) bv[j] = sw[kk * 33 + tn + j];
            #pragma unroll
            for (int x = 0; x < 4; ++x)
                #pragma unroll
                for (int y = 0; y < 4; ++y)
                    acc[x][y] += av[x] * bv[y];
        }
        __syncthreads();
    }
    float* cb = g_c + ((size_t)b * S_ + s0) * NCAP;
    #pragma unroll
    for (int x = 0; x < 4; ++x) {
        float4 vv = make_float4(acc[x][0], acc[x][1], acc[x][2], acc[x][3]);
        *(float4*)(cb + (size_t)(ts + x) * NCAP + tn) = vv;
    }
}

// ---------------- in-place softmax over n (32 contiguous), warp per (b,s) ----------------
__global__ __launch_bounds__(256) void softmax_k() {
    int warp = threadIdx.x >> 5;
    int lane = threadIdx.x & 31;
    size_t bs = (size_t)blockIdx.x * 8 + warp;   // < 32768
    float x = g_c[bs * NCAP + lane];
    float m = x;
    #pragma unroll
    for (int off = 16; off; off >>= 1) m = fmaxf(m, __shfl_xor_sync(0xffffffffu, m, off));
    float e = __expf(x - m);
    float sum = e;
    #pragma unroll
    for (int off = 16; off; off >>= 1) sum += __shfl_xor_sync(0xffffffffu, sum, off);
    g_c[bs * NCAP + lane] = e / sum;
}

// ---------------- v[b,n,i] = sum_s c[b,s,n] * U[b,s,i] ----------------
// per-b GEMM (32n x 512s) @ (512s x 512i), tile 32n x 128i, grid (4,64), block 256.
__global__ __launch_bounds__(256) void v_k(const float* __restrict__ U) {
    int b  = blockIdx.y;
    int i0 = blockIdx.x * 128;
    __shared__ float sc[32 * 33];    // [k(s)][n]
    __shared__ float su[32 * 129];   // [k(s)][i], pad 129
    int tid = threadIdx.x;
    int tn  = (tid & 7) * 4;         // n (0..31)
    int ti  = (tid >> 3) * 4;        // i local (0..127)
    float acc[4][4] = {};
    const float* Ub = U   + (size_t)b * S_ * DIN;
    const float* cb = g_c + (size_t)b * S_ * NCAP;
    for (int k0 = 0; k0 < S_; k0 += 32) {
        {   // c tile 32s x 32n
            int n  = tid & 31;
            int sb = tid >> 5;
            #pragma unroll
            for (int r = 0; r < 4; ++r) {
                int s = sb + r * 8;
                sc[s * 33 + n] = cb[(size_t)(k0 + s) * NCAP + n];
            }
        }
        {   // U tile 32s x 128i
            int il = tid & 127;
            int sb = tid >> 7;       // 0..1
            #pragma unroll
            for (int r = 0; r < 16; ++r) {
                int s = sb + r * 2;
                su[s * 129 + il] = Ub[(size_t)(k0 + s) * DIN + i0 + il];
            }
        }
        __syncthreads();
        #pragma unroll
        for (int kk = 0; kk < 32; ++kk) {
            float av[4], bv[4];
            #pragma unroll
            for (int j = 0; j < 4; ++j) av[j] = sc[kk * 33 + tn + j];
            #pragma unroll
            for (int j = 0; j < 4; ++j) bv[j] = su[kk * 129 + ti + j];
            #pragma unroll
            for (int x = 0; x < 4; ++x)
                #pragma unroll
                for (int y = 0; y < 4; ++y)
                    acc[x][y] += av[x] * bv[y];
        }
        __syncthreads();
    }
    float* vb = g_v + (size_t)b * NCAP * DIN + i0;
    #pragma unroll
    for (int x = 0; x < 4; ++x) {
        float4 vv = make_float4(acc[x][0], acc[x][1], acc[x][2], acc[x][3]);
        *(float4*)(vb + (size_t)(tn + x) * DIN + ti) = vv;
    }
}

// ---------------- launch ----------------
extern "C" void kernel_launch(void* const* d_in, const int* in_sizes, int n_in,
                              void* d_out, int out_size) {
    const float* U = (const float*)d_in[0];   // (64, 512, 512)
    const float* W = (const float*)d_in[1];   // (512, 2048)
    float* out = (float*)d_out;               // (64, 32, 64)

    colsum_k<<<dim3(4, B_), 128>>>(U);
    out_k<<<dim3(8, NCAP), 256>>>(W, out, 1);          // iteration 0 (uniform c)
    for (int it = 0; it < 2; ++it) {
        w_k<<<dim3(8, NCAP), 512>>>(out, W);
        blog_k<<<dim3(4, B_), 256>>>(U);
        softmax_k<<<(B_ * S_) / 8, 256>>>();
        v_k<<<dim3(4, B_), 256>>>(U);
        out_k<<<dim3(8, NCAP), 256>>>(W, out, 0);      // iterations 1, 2
    }
}

// round 3
// speedup vs baseline: 1.5644x; 1.5644x over previous
#include <cuda_runtime.h>

#define B_    64
#define S_    512
#define DIN   512
#define NCAP  32
#define DCAP  64
#define EPSQ  1e-7f

// ---------------- scratch (device globals; no allocations) ----------------
__device__ float g_Wt[NCAP * DCAP * DIN];  // W transposed: [n][d][i]
__device__ float g_tp[4 * B_ * DIN];       // partial column sums of U
__device__ float g_w[B_ * DIN * NCAP];     // w[b][i][n]  (n contiguous for blog B-tiles)
__device__ float g_c[B_ * S_ * NCAP];      // c[b][s][n]  (post-softmax coupling coeffs)
__device__ float g_v[B_ * NCAP * DIN];     // v[b][n][i]

// ---------------- Wt[n][d][i] = W[i][n*64+d], via smem 64x64 tiles ----------------
__global__ __launch_bounds__(256) void transpose_k(const float* __restrict__ W) {
    int n  = blockIdx.y;
    int i0 = blockIdx.x * 64;
    __shared__ float sm[64 * 65];
    int t = threadIdx.x;
    #pragma unroll
    for (int r = 0; r < 16; ++r) {
        int idx = r * 256 + t;
        int d = idx & 63, ii = idx >> 6;
        sm[d * 65 + ii] = W[(size_t)(i0 + ii) * 2048 + n * 64 + d];
    }
    __syncthreads();
    #pragma unroll
    for (int r = 0; r < 16; ++r) {
        int idx = r * 256 + t;
        int ii = idx & 63, d = idx >> 6;
        g_Wt[((size_t)n * 64 + d) * 512 + i0 + ii] = sm[d * 65 + ii];
    }
}

// ---------------- partial colsum: g_tp[sc][b][i] = sum_{s in chunk} U[b,s,i] ----------------
__global__ __launch_bounds__(128) void colsum_k(const float* __restrict__ U) {
    int b = blockIdx.x, sc = blockIdx.y;
    const float4* p = (const float4*)(U + ((size_t)b * S_ + sc * 128) * DIN) + threadIdx.x;
    float4 a = make_float4(0.f, 0.f, 0.f, 0.f);
    #pragma unroll 8
    for (int s = 0; s < 128; ++s) {
        float4 f = p[(size_t)s * 128];
        a.x += f.x; a.y += f.y; a.z += f.z; a.w += f.w;
    }
    *(float4*)(g_tp + ((size_t)sc * B_ + b) * DIN + threadIdx.x * 4) = a;
}

// ---------------- outputs[b,n,:] = squash(v[b,n,:] @ Wt[n]) ----------------
// grid (n=32, bgroup=8), block 256. Wt[n] (128KB) stays in L1 across the 8 b's.
__global__ __launch_bounds__(256) void out_k(float* __restrict__ out, int bcast) {
    int n  = blockIdx.x;
    int b0 = blockIdx.y * 8;
    __shared__ __align__(16) float sv[DIN];
    __shared__ float so[DCAP];
    int t = threadIdx.x, w = t >> 5, lane = t & 31;
    for (int bb = 0; bb < 8; ++bb) {
        int b = b0 + bb;
        #pragma unroll
        for (int r = 0; r < 2; ++r) {
            int idx = t + r * 256;
            if (bcast) {
                sv[idx] = g_tp[(size_t)b * DIN + idx]
                        + g_tp[((size_t)B_ + b) * DIN + idx]
                        + g_tp[((size_t)2 * B_ + b) * DIN + idx]
                        + g_tp[((size_t)3 * B_ + b) * DIN + idx];
            } else {
                sv[idx] = g_v[((size_t)b * NCAP + n) * DIN + idx];
            }
        }
        __syncthreads();
        #pragma unroll
        for (int dd = 0; dd < 8; ++dd) {
            int d = dd * 8 + w;
            const float4* wp = (const float4*)(g_Wt + ((size_t)n * DCAP + d) * DIN);
            const float4* vp = (const float4*)sv;
            float acc = 0.f;
            #pragma unroll
            for (int q = 0; q < 4; ++q) {
                float4 wv = wp[lane + q * 32];
                float4 vv = vp[lane + q * 32];
                acc += wv.x * vv.x + wv.y * vv.y + wv.z * vv.z + wv.w * vv.w;
            }
            #pragma unroll
            for (int off = 16; off; off >>= 1) acc += __shfl_xor_sync(0xffffffffu, acc, off);
            if (lane == 0) so[d] = acc;
        }
        __syncthreads();
        if (w == 0) {
            float o1 = so[lane], o2 = so[lane + 32];
            if (bcast) { o1 *= (1.f / 32.f); o2 *= (1.f / 32.f); }
            float sq = o1 * o1 + o2 * o2;
            #pragma unroll
            for (int off = 16; off; off >>= 1) sq += __shfl_xor_sync(0xffffffffu, sq, off);
            float rn = rsqrtf(sq + EPSQ);
            out[((size_t)b * NCAP + n) * DCAP + lane]      = o1 * rn;
            out[((size_t)b * NCAP + n) * DCAP + lane + 32] = o2 * rn;
        }
        __syncthreads();
    }
}

// ---------------- w[b,i,n] = sum_d out[b,n,d] * Wt[n,d,i] ----------------
// grid (n=32, bgroup=8), block 512 (thread = i). Coalesced Wt rows, L1 reuse across b.
__global__ __launch_bounds__(512) void w_k(const float* __restrict__ outp) {
    int n  = blockIdx.x;
    int b0 = blockIdx.y * 8;
    __shared__ float so[DCAP];
    int i = threadIdx.x;
    const float* Wn = g_Wt + (size_t)n * DCAP * DIN;
    for (int bb = 0; bb < 8; ++bb) {
        int b = b0 + bb;
        if (i < DCAP) so[i] = outp[((size_t)b * NCAP + n) * DCAP + i];
        __syncthreads();
        float acc = 0.f;
        #pragma unroll 16
        for (int d = 0; d < DCAP; ++d) acc += so[d] * Wn[(size_t)d * DIN + i];
        g_w[((size_t)b * DIN + i) * NCAP + n] = acc;
        __syncthreads();
    }
}

// ---------------- fused: logits[b,s,n] = U[b,s,:]·w[b,n,:]  ->  softmax over n -> g_c ----
// grid (4 s-tiles, 64 b), block 256, tile 128s x 32n, thread 4x4, pipelined k-chunks of 32.
__global__ __launch_bounds__(256) void blogsm_k(const float* __restrict__ U) {
    int s0 = blockIdx.x * 128;
    int b  = blockIdx.y;
    __shared__ __align__(16) float su[32 * 132];  // [k][s]
    __shared__ __align__(16) float sw[32 * 36];   // [k][n]
    int t  = threadIdx.x;
    int tn = (t & 7) * 4, ts = (t >> 3) * 4;
    int s_l = t >> 1, kh = (t & 1) * 16;          // U loader: 2 threads per s-row
    int kr  = t >> 3, n4 = (t & 7) * 4;           // w loader
    const float* Ub    = U   + (size_t)b * S_ * DIN + (size_t)(s0 + s_l) * DIN;
    const float* wbase = g_w + (size_t)b * DIN * NCAP;
    float4 ua[4], wv;
    #pragma unroll
    for (int j = 0; j < 4; ++j) ua[j] = *(const float4*)(Ub + kh + 4 * j);
    wv = *(const float4*)(wbase + (size_t)kr * NCAP + n4);
    float acc[4][4] = {};
    #pragma unroll 1
    for (int c = 0; c < 16; ++c) {
        __syncthreads();
        #pragma unroll
        for (int j = 0; j < 4; ++j) {
            int kb = kh + 4 * j;
            su[(kb + 0) * 132 + s_l] = ua[j].x;
            su[(kb + 1) * 132 + s_l] = ua[j].y;
            su[(kb + 2) * 132 + s_l] = ua[j].z;
            su[(kb + 3) * 132 + s_l] = ua[j].w;
        }
        *(float4*)&sw[kr * 36 + n4] = wv;
        __syncthreads();
        if (c < 15) {
            int k0 = (c + 1) * 32;
            #pragma unroll
            for (int j = 0; j < 4; ++j) ua[j] = *(const float4*)(Ub + k0 + kh + 4 * j);
            wv = *(const float4*)(wbase + (size_t)(k0 + kr) * NCAP + n4);
        }
        #pragma unroll
        for (int kk = 0; kk < 32; ++kk) {
            float4 a  = *(const float4*)&su[kk * 132 + ts];
            float4 bb = *(const float4*)&sw[kk * 36 + tn];
            float av[4] = {a.x, a.y, a.z, a.w};
            float bv[4] = {bb.x, bb.y, bb.z, bb.w};
            #pragma unroll
            for (int x = 0; x < 4; ++x)
                #pragma unroll
                for (int y = 0; y < 4; ++y)
                    acc[x][y] += av[x] * bv[y];
        }
    }
    // register softmax over n (row spread across 8 lanes: xor 1,2,4 stays in-group)
    float* cb = g_c + ((size_t)b * S_ + s0) * NCAP;
    #pragma unroll
    for (int x = 0; x < 4; ++x) {
        float m = fmaxf(fmaxf(acc[x][0], acc[x][1]), fmaxf(acc[x][2], acc[x][3]));
        m = fmaxf(m, __shfl_xor_sync(0xffffffffu, m, 1));
        m = fmaxf(m, __shfl_xor_sync(0xffffffffu, m, 2));
        m = fmaxf(m, __shfl_xor_sync(0xffffffffu, m, 4));
        float e0 = __expf(acc[x][0] - m), e1 = __expf(acc[x][1] - m);
        float e2 = __expf(acc[x][2] - m), e3 = __expf(acc[x][3] - m);
        float sm = e0 + e1 + e2 + e3;
        sm += __shfl_xor_sync(0xffffffffu, sm, 1);
        sm += __shfl_xor_sync(0xffffffffu, sm, 2);
        sm += __shfl_xor_sync(0xffffffffu, sm, 4);
        float inv = 1.f / sm;
        *(float4*)(cb + (size_t)(ts + x) * NCAP + tn) =
            make_float4(e0 * inv, e1 * inv, e2 * inv, e3 * inv);
    }
}

// ---------------- v[b,n,i] = sum_s c[b,s,n] * U[b,s,i] ----------------
// grid (4 i-tiles, 64 b), block 256, tile 32n x 128i, thread 4x4, pipelined s-chunks of 32.
__global__ __launch_bounds__(256) void v_k(const float* __restrict__ U) {
    int i0 = blockIdx.x * 128;
    int b  = blockIdx.y;
    __shared__ __align__(16) float su[32 * 132];  // [s][i]
    __shared__ __align__(16) float sc[32 * 36];   // [s][n]
    int t  = threadIdx.x;
    int tn = (t & 7) * 4, ti = (t >> 3) * 4;
    int s_u = t >> 3, c0 = (t & 7) * 16;          // U loader: 8 threads per s-row
    int n4  = (t & 7) * 4;                        // c loader (same s_u)
    const float* Ub = U   + (size_t)b * S_ * DIN;
    const float* cb = g_c + (size_t)b * S_ * NCAP;
    float4 uv[4], cv;
    #pragma unroll
    for (int j = 0; j < 4; ++j)
        uv[j] = *(const float4*)(Ub + (size_t)s_u * DIN + i0 + c0 + 4 * j);
    cv = *(const float4*)(cb + (size_t)s_u * NCAP + n4);
    float acc[4][4] = {};
    #pragma unroll 1
    for (int c = 0; c < 16; ++c) {
        __syncthreads();
        #pragma unroll
        for (int j = 0; j < 4; ++j) *(float4*)&su[s_u * 132 + c0 + 4 * j] = uv[j];
        *(float4*)&sc[s_u * 36 + n4] = cv;
        __syncthreads();
        if (c < 15) {
            int k0 = (c + 1) * 32;
            #pragma unroll
            for (int j = 0; j < 4; ++j)
                uv[j] = *(const float4*)(Ub + (size_t)(k0 + s_u) * DIN + i0 + c0 + 4 * j);
            cv = *(const float4*)(cb + (size_t)(k0 + s_u) * NCAP + n4);
        }
        #pragma unroll
        for (int kk = 0; kk < 32; ++kk) {
            float4 a  = *(const float4*)&sc[kk * 36 + tn];
            float4 bb = *(const float4*)&su[kk * 132 + ti];
            float av[4] = {a.x, a.y, a.z, a.w};
            float bv[4] = {bb.x, bb.y, bb.z, bb.w};
            #pragma unroll
            for (int x = 0; x < 4; ++x)
                #pragma unroll
                for (int y = 0; y < 4; ++y)
                    acc[x][y] += av[x] * bv[y];
        }
    }
    float* vb = g_v + (size_t)b * NCAP * DIN + i0;
    #pragma unroll
    for (int x = 0; x < 4; ++x)
        *(float4*)(vb + (size_t)(tn + x) * DIN + ti) =
            make_float4(acc[x][0], acc[x][1], acc[x][2], acc[x][3]);
}

// ---------------- launch ----------------
extern "C" void kernel_launch(void* const* d_in, const int* in_sizes, int n_in,
                              void* d_out, int out_size) {
    const float* U = (const float*)d_in[0];   // (64, 512, 512)
    const float* W = (const float*)d_in[1];   // (512, 2048)
    float* out = (float*)d_out;               // (64, 32, 64)

    transpose_k<<<dim3(8, 32), 256>>>(W);
    colsum_k<<<dim3(64, 4), 128>>>(U);
    out_k<<<dim3(32, 8), 256>>>(out, 1);           // iteration 0 (uniform c)
    for (int it = 0; it < 2; ++it) {
        w_k<<<dim3(32, 8), 512>>>(out);
        blogsm_k<<<dim3(4, 64), 256>>>(U);
        v_k<<<dim3(4, 64), 256>>>(U);
        out_k<<<dim3(32, 8), 256>>>(out, 0);       // iterations 1, 2
    }
}

// round 4
// speedup vs baseline: 1.7960x; 1.1480x over previous
#include <cuda_runtime.h>

#define B_    64
#define S_    512
#define DIN   512
#define NCAP  32
#define DCAP  64
#define EPSQ  1e-7f

// ---------------- scratch (device globals; no allocations) ----------------
__device__ float g_Wt[NCAP * DCAP * DIN];  // W transposed: [n][d][i]
__device__ float g_tp[4 * B_ * DIN];       // partial column sums of U
__device__ float g_w[B_ * DIN * NCAP];     // w[b][i][n]  (n contiguous for blog B-tiles)
__device__ float g_c[B_ * S_ * NCAP];      // c[b][s][n]  (post-softmax coupling coeffs)
__device__ float g_v[B_ * NCAP * DIN];     // v[b][n][i]

// ---------------- Wt[n][d][i] = W[i][n*64+d], via smem 64x64 tiles ----------------
__global__ __launch_bounds__(256) void transpose_k(const float* __restrict__ W) {
    int n  = blockIdx.y;
    int i0 = blockIdx.x * 64;
    __shared__ float sm[64 * 65];
    int t = threadIdx.x;
    #pragma unroll
    for (int r = 0; r < 16; ++r) {
        int idx = r * 256 + t;
        int d = idx & 63, ii = idx >> 6;
        sm[d * 65 + ii] = W[(size_t)(i0 + ii) * 2048 + n * 64 + d];
    }
    __syncthreads();
    #pragma unroll
    for (int r = 0; r < 16; ++r) {
        int idx = r * 256 + t;
        int ii = idx & 63, d = idx >> 6;
        g_Wt[((size_t)n * 64 + d) * 512 + i0 + ii] = sm[d * 65 + ii];
    }
}

// ---------------- partial colsum: g_tp[sc][b][i] = sum_{s in chunk} U[b,s,i] ----------------
__global__ __launch_bounds__(128) void colsum_k(const float* __restrict__ U) {
    int b = blockIdx.x, sc = blockIdx.y;
    const float4* p = (const float4*)(U + ((size_t)b * S_ + sc * 128) * DIN) + threadIdx.x;
    float4 a = make_float4(0.f, 0.f, 0.f, 0.f);
    #pragma unroll 8
    for (int s = 0; s < 128; ++s) {
        float4 f = p[(size_t)s * 128];
        a.x += f.x; a.y += f.y; a.z += f.z; a.w += f.w;
    }
    *(float4*)(g_tp + ((size_t)sc * B_ + b) * DIN + threadIdx.x * 4) = a;
}

// ---------------- fused out + w ----------------
// out[b,n,:] = squash(v[b,n,:] @ Wt[n]); then (if dow) w[b,i,n] = sum_d out*Wt[n,d,i].
// grid (n=32, bgroup=8), block 512. All 8 b's processed per pass over Wt[n]
// (8 FMA per Wt load); second pass hits L1 (128KB tile resident).
__global__ __launch_bounds__(512) void outw_k(float* __restrict__ out, int bcast, int dow) {
    int n  = blockIdx.x;
    int b0 = blockIdx.y * 8;
    __shared__ __align__(16) float sv[8][DIN];   // 16KB: v (or colsum) vectors
    __shared__ float so[8][DCAP];                // squashed outputs
    int t = threadIdx.x, w = t >> 5, lane = t & 31;
    const float* Wn = g_Wt + (size_t)n * DCAP * DIN;

    // stage the 8 v-vectors
    #pragma unroll
    for (int r = 0; r < 8; ++r) {
        int idx = r * 512 + t;
        int bb = idx >> 9, pos = idx & 511;
        int b = b0 + bb;
        float val;
        if (bcast)
            val = g_tp[(size_t)b * DIN + pos]
                + g_tp[((size_t)B_ + b) * DIN + pos]
                + g_tp[((size_t)2 * B_ + b) * DIN + pos]
                + g_tp[((size_t)3 * B_ + b) * DIN + pos];
        else
            val = g_v[((size_t)b * NCAP + n) * DIN + pos];
        sv[bb][pos] = val;
    }
    __syncthreads();

    // pass 1: warp w handles d-rows {w, w+16, w+32, w+48}; 8 b-accumulators per row
    #pragma unroll
    for (int r = 0; r < 4; ++r) {
        int d = r * 16 + w;
        const float4* wp = (const float4*)(Wn + (size_t)d * DIN);
        float acc[8] = {};
        #pragma unroll
        for (int q = 0; q < 4; ++q) {
            float4 wv = wp[lane + q * 32];
            #pragma unroll
            for (int bb = 0; bb < 8; ++bb) {
                float4 vv = ((const float4*)sv[bb])[lane + q * 32];
                acc[bb] += wv.x * vv.x + wv.y * vv.y + wv.z * vv.z + wv.w * vv.w;
            }
        }
        #pragma unroll
        for (int bb = 0; bb < 8; ++bb) {
            #pragma unroll
            for (int off = 16; off; off >>= 1)
                acc[bb] += __shfl_xor_sync(0xffffffffu, acc[bb], off);
        }
        if (lane == 0) {
            #pragma unroll
            for (int bb = 0; bb < 8; ++bb) so[bb][d] = acc[bb];
        }
    }
    __syncthreads();

    // squash: warp bb (<8) normalizes its b's 64-vector
    if (w < 8) {
        int b = b0 + w;
        float o1 = so[w][lane], o2 = so[w][lane + 32];
        if (bcast) { o1 *= (1.f / 32.f); o2 *= (1.f / 32.f); }
        float sq = o1 * o1 + o2 * o2;
        #pragma unroll
        for (int off = 16; off; off >>= 1) sq += __shfl_xor_sync(0xffffffffu, sq, off);
        float rn = rsqrtf(sq + EPSQ);
        o1 *= rn; o2 *= rn;
        out[((size_t)b * NCAP + n) * DCAP + lane]      = o1;
        out[((size_t)b * NCAP + n) * DCAP + lane + 32] = o2;
        so[w][lane]      = o1;
        so[w][lane + 32] = o2;
    }
    __syncthreads();

    // pass 2: w[b,i,n], thread = i, single L1-resident pass over Wt[n]
    if (dow) {
        int i = t;
        float acc[8] = {};
        #pragma unroll 8
        for (int d = 0; d < DCAP; ++d) {
            float wt = Wn[(size_t)d * DIN + i];
            #pragma unroll
            for (int bb = 0; bb < 8; ++bb) acc[bb] += so[bb][d] * wt;
        }
        #pragma unroll
        for (int bb = 0; bb < 8; ++bb)
            g_w[((size_t)(b0 + bb) * DIN + i) * NCAP + n] = acc[bb];
    }
}

// ---------------- fused: logits[b,s,n] = U[b,s,:]·w[b,n,:]  ->  softmax over n -> g_c ----
// grid (4 s-tiles, 64 b), block 256, tile 128s x 32n, thread 4x4, pipelined k-chunks of 32.
__global__ __launch_bounds__(256) void blogsm_k(const float* __restrict__ U) {
    int s0 = blockIdx.x * 128;
    int b  = blockIdx.y;
    __shared__ __align__(16) float su[32 * 132];  // [k][s]
    __shared__ __align__(16) float sw[32 * 36];   // [k][n]
    int t  = threadIdx.x;
    int tn = (t & 7) * 4, ts = (t >> 3) * 4;
    int s_l = t >> 1, kh = (t & 1) * 16;          // U loader: 2 threads per s-row
    int kr  = t >> 3, n4 = (t & 7) * 4;           // w loader
    const float* Ub    = U   + (size_t)b * S_ * DIN + (size_t)(s0 + s_l) * DIN;
    const float* wbase = g_w + (size_t)b * DIN * NCAP;
    float4 ua[4], wv;
    #pragma unroll
    for (int j = 0; j < 4; ++j) ua[j] = *(const float4*)(Ub + kh + 4 * j);
    wv = *(const float4*)(wbase + (size_t)kr * NCAP + n4);
    float acc[4][4] = {};
    #pragma unroll 1
    for (int c = 0; c < 16; ++c) {
        __syncthreads();
        #pragma unroll
        for (int j = 0; j < 4; ++j) {
            int kb = kh + 4 * j;
            su[(kb + 0) * 132 + s_l] = ua[j].x;
            su[(kb + 1) * 132 + s_l] = ua[j].y;
            su[(kb + 2) * 132 + s_l] = ua[j].z;
            su[(kb + 3) * 132 + s_l] = ua[j].w;
        }
        *(float4*)&sw[kr * 36 + n4] = wv;
        __syncthreads();
        if (c < 15) {
            int k0 = (c + 1) * 32;
            #pragma unroll
            for (int j = 0; j < 4; ++j) ua[j] = *(const float4*)(Ub + k0 + kh + 4 * j);
            wv = *(const float4*)(wbase + (size_t)(k0 + kr) * NCAP + n4);
        }
        #pragma unroll
        for (int kk = 0; kk < 32; ++kk) {
            float4 a  = *(const float4*)&su[kk * 132 + ts];
            float4 bb = *(const float4*)&sw[kk * 36 + tn];
            float av[4] = {a.x, a.y, a.z, a.w};
            float bv[4] = {bb.x, bb.y, bb.z, bb.w};
            #pragma unroll
            for (int x = 0; x < 4; ++x)
                #pragma unroll
                for (int y = 0; y < 4; ++y)
                    acc[x][y] += av[x] * bv[y];
        }
    }
    // register softmax over n (row spread across 8 lanes: xor 1,2,4 stays in-group)
    float* cb = g_c + ((size_t)b * S_ + s0) * NCAP;
    #pragma unroll
    for (int x = 0; x < 4; ++x) {
        float m = fmaxf(fmaxf(acc[x][0], acc[x][1]), fmaxf(acc[x][2], acc[x][3]));
        m = fmaxf(m, __shfl_xor_sync(0xffffffffu, m, 1));
        m = fmaxf(m, __shfl_xor_sync(0xffffffffu, m, 2));
        m = fmaxf(m, __shfl_xor_sync(0xffffffffu, m, 4));
        float e0 = __expf(acc[x][0] - m), e1 = __expf(acc[x][1] - m);
        float e2 = __expf(acc[x][2] - m), e3 = __expf(acc[x][3] - m);
        float sm = e0 + e1 + e2 + e3;
        sm += __shfl_xor_sync(0xffffffffu, sm, 1);
        sm += __shfl_xor_sync(0xffffffffu, sm, 2);
        sm += __shfl_xor_sync(0xffffffffu, sm, 4);
        float inv = 1.f / sm;
        *(float4*)(cb + (size_t)(ts + x) * NCAP + tn) =
            make_float4(e0 * inv, e1 * inv, e2 * inv, e3 * inv);
    }
}

// ---------------- v[b,n,i] = sum_s c[b,s,n] * U[b,s,i] ----------------
// grid (4 i-tiles, 64 b), block 256, tile 32n x 128i, thread 4x4, pipelined s-chunks of 32.
__global__ __launch_bounds__(256) void v_k(const float* __restrict__ U) {
    int i0 = blockIdx.x * 128;
    int b  = blockIdx.y;
    __shared__ __align__(16) float su[32 * 132];  // [s][i]
    __shared__ __align__(16) float sc[32 * 36];   // [s][n]
    int t  = threadIdx.x;
    int tn = (t & 7) * 4, ti = (t >> 3) * 4;
    int s_u = t >> 3, c0 = (t & 7) * 16;          // U loader: 8 threads per s-row
    int n4  = (t & 7) * 4;                        // c loader (same s_u)
    const float* Ub = U   + (size_t)b * S_ * DIN;
    const float* cb = g_c + (size_t)b * S_ * NCAP;
    float4 uv[4], cv;
    #pragma unroll
    for (int j = 0; j < 4; ++j)
        uv[j] = *(const float4*)(Ub + (size_t)s_u * DIN + i0 + c0 + 4 * j);
    cv = *(const float4*)(cb + (size_t)s_u * NCAP + n4);
    float acc[4][4] = {};
    #pragma unroll 1
    for (int c = 0; c < 16; ++c) {
        __syncthreads();
        #pragma unroll
        for (int j = 0; j < 4; ++j) *(float4*)&su[s_u * 132 + c0 + 4 * j] = uv[j];
        *(float4*)&sc[s_u * 36 + n4] = cv;
        __syncthreads();
        if (c < 15) {
            int k0 = (c + 1) * 32;
            #pragma unroll
            for (int j = 0; j < 4; ++j)
                uv[j] = *(const float4*)(Ub + (size_t)(k0 + s_u) * DIN + i0 + c0 + 4 * j);
            cv = *(const float4*)(cb + (size_t)(k0 + s_u) * NCAP + n4);
        }
        #pragma unroll
        for (int kk = 0; kk < 32; ++kk) {
            float4 a  = *(const float4*)&sc[kk * 36 + tn];
            float4 bb = *(const float4*)&su[kk * 132 + ti];
            float av[4] = {a.x, a.y, a.z, a.w};
            float bv[4] = {bb.x, bb.y, bb.z, bb.w};
            #pragma unroll
            for (int x = 0; x < 4; ++x)
                #pragma unroll
                for (int y = 0; y < 4; ++y)
                    acc[x][y] += av[x] * bv[y];
        }
    }
    float* vb = g_v + (size_t)b * NCAP * DIN + i0;
    #pragma unroll
    for (int x = 0; x < 4; ++x)
        *(float4*)(vb + (size_t)(tn + x) * DIN + ti) =
            make_float4(acc[x][0], acc[x][1], acc[x][2], acc[x][3]);
}

// ---------------- launch ----------------
extern "C" void kernel_launch(void* const* d_in, const int* in_sizes, int n_in,
                              void* d_out, int out_size) {
    const float* U = (const float*)d_in[0];   // (64, 512, 512)
    const float* W = (const float*)d_in[1];   // (512, 2048)
    float* out = (float*)d_out;               // (64, 32, 64)

    transpose_k<<<dim3(8, 32), 256>>>(W);
    colsum_k<<<dim3(64, 4), 128>>>(U);
    outw_k<<<dim3(32, 8), 512>>>(out, 1, 1);       // iteration 0 (uniform c) + w0
    for (int it = 0; it < 2; ++it) {
        blogsm_k<<<dim3(4, 64), 256>>>(U);
        v_k<<<dim3(4, 64), 256>>>(U);
        outw_k<<<dim3(32, 8), 512>>>(out, 0, it == 0);  // out + (w for iter 1 only)
    }
}

// round 5
// speedup vs baseline: 2.2174x; 1.2346x over previous
#include <cuda_runtime.h>

#define B_    64
#define S_    512
#define DIN   512
#define NCAP  32
#define DCAP  64
#define EPSQ  1e-7f

// ---------------- scratch (device globals; no allocations) ----------------
__device__ float g_Wt[NCAP * DCAP * DIN];  // W transposed: [n][d][i]
__device__ float g_tp[4 * B_ * DIN];       // partial column sums of U
__device__ float g_w[B_ * DIN * NCAP];     // w[b][i][n]
__device__ float g_c[B_ * S_ * NCAP];      // c[b][s][n]
__device__ float g_v[B_ * NCAP * DIN];     // v[b][n][i]

// ---------------- prep: blocks 0..255 transpose W, 256..511 colsum U ----------------
__global__ __launch_bounds__(256) void prep_k(const float* __restrict__ U,
                                              const float* __restrict__ W) {
    int t = threadIdx.x;
    if (blockIdx.x < 256) {
        int n  = blockIdx.x >> 3;
        int i0 = (blockIdx.x & 7) * 64;
        __shared__ float sm[64 * 65];
        #pragma unroll
        for (int r = 0; r < 16; ++r) {
            int idx = r * 256 + t;
            int d = idx & 63, ii = idx >> 6;
            sm[d * 65 + ii] = W[(size_t)(i0 + ii) * 2048 + n * 64 + d];
        }
        __syncthreads();
        #pragma unroll
        for (int r = 0; r < 16; ++r) {
            int idx = r * 256 + t;
            int ii = idx & 63, d = idx >> 6;
            g_Wt[((size_t)n * 64 + d) * 512 + i0 + ii] = sm[d * 65 + ii];
        }
    } else {
        int idx = blockIdx.x - 256;
        int b = idx & 63, sc = idx >> 6;
        const float2* p = (const float2*)(U + ((size_t)b * S_ + sc * 128) * DIN) + t;
        float2 a = make_float2(0.f, 0.f);
        #pragma unroll 8
        for (int s = 0; s < 128; ++s) {
            float2 f = p[(size_t)s * 256];
            a.x += f.x; a.y += f.y;
        }
        *(float2*)(g_tp + ((size_t)sc * B_ + b) * DIN + t * 2) = a;
    }
}

// ---------------- fused out + w (unchanged from R3) ----------------
__global__ __launch_bounds__(512) void outw_k(float* __restrict__ out, int bcast, int dow) {
    int n  = blockIdx.x;
    int b0 = blockIdx.y * 8;
    __shared__ __align__(16) float sv[8][DIN];
    __shared__ float so[8][DCAP];
    int t = threadIdx.x, w = t >> 5, lane = t & 31;
    const float* Wn = g_Wt + (size_t)n * DCAP * DIN;

    #pragma unroll
    for (int r = 0; r < 8; ++r) {
        int idx = r * 512 + t;
        int bb = idx >> 9, pos = idx & 511;
        int b = b0 + bb;
        float val;
        if (bcast)
            val = g_tp[(size_t)b * DIN + pos]
                + g_tp[((size_t)B_ + b) * DIN + pos]
                + g_tp[((size_t)2 * B_ + b) * DIN + pos]
                + g_tp[((size_t)3 * B_ + b) * DIN + pos];
        else
            val = g_v[((size_t)b * NCAP + n) * DIN + pos];
        sv[bb][pos] = val;
    }
    __syncthreads();

    #pragma unroll
    for (int r = 0; r < 4; ++r) {
        int d = r * 16 + w;
        const float4* wp = (const float4*)(Wn + (size_t)d * DIN);
        float acc[8] = {};
        #pragma unroll
        for (int q = 0; q < 4; ++q) {
            float4 wv = wp[lane + q * 32];
            #pragma unroll
            for (int bb = 0; bb < 8; ++bb) {
                float4 vv = ((const float4*)sv[bb])[lane + q * 32];
                acc[bb] += wv.x * vv.x + wv.y * vv.y + wv.z * vv.z + wv.w * vv.w;
            }
        }
        #pragma unroll
        for (int bb = 0; bb < 8; ++bb) {
            #pragma unroll
            for (int off = 16; off; off >>= 1)
                acc[bb] += __shfl_xor_sync(0xffffffffu, acc[bb], off);
        }
        if (lane == 0) {
            #pragma unroll
            for (int bb = 0; bb < 8; ++bb) so[bb][d] = acc[bb];
        }
    }
    __syncthreads();

    if (w < 8) {
        int b = b0 + w;
        float o1 = so[w][lane], o2 = so[w][lane + 32];
        if (bcast) { o1 *= (1.f / 32.f); o2 *= (1.f / 32.f); }
        float sq = o1 * o1 + o2 * o2;
        #pragma unroll
        for (int off = 16; off; off >>= 1) sq += __shfl_xor_sync(0xffffffffu, sq, off);
        float rn = rsqrtf(sq + EPSQ);
        o1 *= rn; o2 *= rn;
        out[((size_t)b * NCAP + n) * DCAP + lane]      = o1;
        out[((size_t)b * NCAP + n) * DCAP + lane + 32] = o2;
        so[w][lane]      = o1;
        so[w][lane + 32] = o2;
    }
    __syncthreads();

    if (dow) {
        int i = t;
        float acc[8] = {};
        #pragma unroll 8
        for (int d = 0; d < DCAP; ++d) {
            float wt = Wn[(size_t)d * DIN + i];
            #pragma unroll
            for (int bb = 0; bb < 8; ++bb) acc[bb] += so[bb][d] * wt;
        }
        #pragma unroll
        for (int bb = 0; bb < 8; ++bb)
            g_w[((size_t)(b0 + bb) * DIN + i) * NCAP + n] = acc[bb];
    }
}

// ---------------- fused logits+softmax: tile 256s x 32n, thread 8s x 4n ----------------
// su [s][k] (natural, k-vectorized reads), sw [k][n]. grid (2,64) = 128 blocks.
__global__ __launch_bounds__(256, 2) void blogsm_k(const float* __restrict__ U) {
    int s0 = blockIdx.x * 256;
    int b  = blockIdx.y;
    __shared__ __align__(16) float su[256 * 36];  // [s][k], stride 36
    __shared__ __align__(16) float sw[32 * 36];   // [k][n], stride 36
    int t  = threadIdx.x;
    int tn = (t & 7) * 4, ts = (t >> 3) * 8;
    int lrow = t >> 3, lk = (t & 7) * 4;          // loader: 8 lanes per s-row
    const float* Ub    = U   + (size_t)b * S_ * DIN;
    const float* wbase = g_w + (size_t)b * DIN * NCAP;
    float4 ua[8], wv;
    #pragma unroll
    for (int j = 0; j < 8; ++j)
        ua[j] = *(const float4*)(Ub + (size_t)(s0 + lrow + 32 * j) * DIN + lk);
    wv = *(const float4*)(wbase + (size_t)lrow * NCAP + tn);
    float acc[8][4] = {};
    #pragma unroll 1
    for (int c = 0; c < 16; ++c) {
        __syncthreads();
        #pragma unroll
        for (int j = 0; j < 8; ++j)
            *(float4*)&su[(lrow + 32 * j) * 36 + lk] = ua[j];
        *(float4*)&sw[lrow * 36 + tn] = wv;
        __syncthreads();
        if (c < 15) {
            int k0 = (c + 1) * 32;
            #pragma unroll
            for (int j = 0; j < 8; ++j)
                ua[j] = *(const float4*)(Ub + (size_t)(s0 + lrow + 32 * j) * DIN + k0 + lk);
            wv = *(const float4*)(wbase + (size_t)(k0 + lrow) * NCAP + tn);
        }
        #pragma unroll
        for (int kk = 0; kk < 32; kk += 4) {
            float4 wv4[4], sv4[8];
            #pragma unroll
            for (int q = 0; q < 4; ++q) wv4[q] = *(const float4*)&sw[(kk + q) * 36 + tn];
            #pragma unroll
            for (int x = 0; x < 8; ++x) sv4[x] = *(const float4*)&su[(ts + x) * 36 + kk];
            #pragma unroll
            for (int q = 0; q < 4; ++q) {
                float4 wq = wv4[q];
                #pragma unroll
                for (int x = 0; x < 8; ++x) {
                    float a = (q == 0) ? sv4[x].x : (q == 1) ? sv4[x].y
                            : (q == 2) ? sv4[x].z : sv4[x].w;
                    acc[x][0] += a * wq.x; acc[x][1] += a * wq.y;
                    acc[x][2] += a * wq.z; acc[x][3] += a * wq.w;
                }
            }
        }
    }
    // softmax over n: each s-row's 32 n spread over 8 lanes (xor 1,2,4)
    float* cb = g_c + ((size_t)b * S_ + s0) * NCAP;
    #pragma unroll
    for (int x = 0; x < 8; ++x) {
        float m = fmaxf(fmaxf(acc[x][0], acc[x][1]), fmaxf(acc[x][2], acc[x][3]));
        m = fmaxf(m, __shfl_xor_sync(0xffffffffu, m, 1));
        m = fmaxf(m, __shfl_xor_sync(0xffffffffu, m, 2));
        m = fmaxf(m, __shfl_xor_sync(0xffffffffu, m, 4));
        float e0 = __expf(acc[x][0] - m), e1 = __expf(acc[x][1] - m);
        float e2 = __expf(acc[x][2] - m), e3 = __expf(acc[x][3] - m);
        float sm = e0 + e1 + e2 + e3;
        sm += __shfl_xor_sync(0xffffffffu, sm, 1);
        sm += __shfl_xor_sync(0xffffffffu, sm, 2);
        sm += __shfl_xor_sync(0xffffffffu, sm, 4);
        float inv = 1.f / sm;
        *(float4*)(cb + (size_t)(ts + x) * NCAP + tn) =
            make_float4(e0 * inv, e1 * inv, e2 * inv, e3 * inv);
    }
}

// ---------------- v: tile 32n x 256i, thread 4n x 8i, grid (2,64) ----------------
__global__ __launch_bounds__(256, 2) void v_k(const float* __restrict__ U) {
    int i0 = blockIdx.x * 256;
    int b  = blockIdx.y;
    __shared__ __align__(16) float su[32 * 260];  // [s][i], stride 260
    __shared__ __align__(16) float sc[32 * 36];   // [s][n], stride 36
    int t  = threadIdx.x;
    int tn = (t & 7) * 4, ti = (t >> 3) * 8;
    int s_u = t >> 3, li = (t & 7) * 4;           // loader: 8 lanes per s-row
    const float* Ub = U   + (size_t)b * S_ * DIN;
    const float* cb = g_c + (size_t)b * S_ * NCAP;
    float4 uv[8], cv;
    #pragma unroll
    for (int j = 0; j < 8; ++j)
        uv[j] = *(const float4*)(Ub + (size_t)s_u * DIN + i0 + li + 32 * j);
    cv = *(const float4*)(cb + (size_t)s_u * NCAP + tn);
    float acc[4][8] = {};
    #pragma unroll 1
    for (int c = 0; c < 16; ++c) {
        __syncthreads();
        #pragma unroll
        for (int j = 0; j < 8; ++j)
            *(float4*)&su[s_u * 260 + li + 32 * j] = uv[j];
        *(float4*)&sc[s_u * 36 + tn] = cv;
        __syncthreads();
        if (c < 15) {
            int k0 = (c + 1) * 32;
            #pragma unroll
            for (int j = 0; j < 8; ++j)
                uv[j] = *(const float4*)(Ub + (size_t)(k0 + s_u) * DIN + i0 + li + 32 * j);
            cv = *(const float4*)(cb + (size_t)(k0 + s_u) * NCAP + tn);
        }
        #pragma unroll
        for (int kk = 0; kk < 32; ++kk) {
            float4 c4 = *(const float4*)&sc[kk * 36 + tn];
            float4 u0 = *(const float4*)&su[kk * 260 + ti];
            float4 u1 = *(const float4*)&su[kk * 260 + ti + 4];
            float cvv[4] = {c4.x, c4.y, c4.z, c4.w};
            float uvv[8] = {u0.x, u0.y, u0.z, u0.w, u1.x, u1.y, u1.z, u1.w};
            #pragma unroll
            for (int y = 0; y < 4; ++y)
                #pragma unroll
                for (int x = 0; x < 8; ++x)
                    acc[y][x] += cvv[y] * uvv[x];
        }
    }
    float* vb = g_v + (size_t)b * NCAP * DIN + i0;
    #pragma unroll
    for (int y = 0; y < 4; ++y) {
        *(float4*)(vb + (size_t)(tn + y) * DIN + ti) =
            make_float4(acc[y][0], acc[y][1], acc[y][2], acc[y][3]);
        *(float4*)(vb + (size_t)(tn + y) * DIN + ti + 4) =
            make_float4(acc[y][4], acc[y][5], acc[y][6], acc[y][7]);
    }
}

// ---------------- launch ----------------
extern "C" void kernel_launch(void* const* d_in, const int* in_sizes, int n_in,
                              void* d_out, int out_size) {
    const float* U = (const float*)d_in[0];   // (64, 512, 512)
    const float* W = (const float*)d_in[1];   // (512, 2048)
    float* out = (float*)d_out;               // (64, 32, 64)

    prep_k<<<512, 256>>>(U, W);
    outw_k<<<dim3(32, 8), 512>>>(out, 1, 1);           // iteration 0 + w0
    for (int it = 0; it < 2; ++it) {
        blogsm_k<<<dim3(2, 64), 256>>>(U);
        v_k<<<dim3(2, 64), 256>>>(U);
        outw_k<<<dim3(32, 8), 512>>>(out, 0, it == 0); // out + (w for iter 1 only)
    }
}